// round 4
// baseline (speedup 1.0000x reference)
#include <cuda_runtime.h>

#define NH 64
#define IN_NODE 128
#define IN_EDGE 32
#define N_MAX 100000
#define E_MAX 1600000
#define SCAN_B 512

typedef unsigned long long ull;

// ---------------- scratch (__device__ globals; no allocation) ----------------
__device__ float d_A[N_MAX * NH];       // h0 / P
__device__ float d_B[N_MAX * NH];       // h1
__device__ float d_Qb[N_MAX * NH];      // Q
__device__ int   d_cnt[N_MAX];
__device__ int   d_off[N_MAX];
__device__ int   d_cur[N_MAX];
__device__ int   d_bsum[(N_MAX + SCAN_B - 1) / SCAN_B];
__device__ int   d_esrc[E_MAX];         // src sorted by dst (CSR adjacency)
__device__ float d_Wec[IN_EDGE * NH];   // folded We@W1c, natural row-major
__device__ float d_b1p[NH];
__device__ float d_w2s[NH];
__device__ float d_c2[1];

// ---------------- f32x2 helpers ----------------
__device__ __forceinline__ ull pk2(float lo, float hi) {
    ull r; asm("mov.b64 %0,{%1,%2};" : "=l"(r) : "f"(lo), "f"(hi)); return r;
}
__device__ __forceinline__ void upk2(ull v, float& lo, float& hi) {
    asm("mov.b64 {%0,%1},%2;" : "=f"(lo), "=f"(hi) : "l"(v));
}
__device__ __forceinline__ ull fma2(ull a, ull b, ull c) {
    ull d; asm("fma.rn.f32x2 %0,%1,%2,%3;" : "=l"(d) : "l"(a), "l"(b), "l"(c)); return d;
}
__device__ __forceinline__ ull add2(ull a, ull b) {
    ull d; asm("add.rn.f32x2 %0,%1,%2;" : "=l"(d) : "l"(a), "l"(b)); return d;
}
__device__ __forceinline__ ull mul2(ull a, ull b) {
    ull d; asm("mul.rn.f32x2 %0,%1,%2;" : "=l"(d) : "l"(a), "l"(b)); return d;
}
__device__ __forceinline__ ull dup2(float x) { return pk2(x, x); }

// ---------------- weight folding ----------------
__global__ void fold_kernel(const float* __restrict__ W1, const float* __restrict__ b1,
                            const float* __restrict__ We, const float* __restrict__ be,
                            const float* __restrict__ W2, const float* __restrict__ b2,
                            const float* __restrict__ Ws, const float* __restrict__ bs) {
    int t = threadIdx.x;
    for (int idx = t; idx < IN_EDGE * NH; idx += blockDim.x) {
        int k = idx >> 6, j = idx & 63;
        float s = 0.f;
        for (int m = 0; m < NH; m++)
            s = fmaf(We[k * NH + m], W1[(IN_NODE + m) * NH + j], s);
        d_Wec[idx] = s;
    }
    if (t < NH) {
        float s = b1[t];
        for (int m = 0; m < NH; m++) s = fmaf(be[m], W1[(IN_NODE + m) * NH + t], s);
        d_b1p[t] = s;
        float w = 0.f;
        for (int k = 0; k < NH; k++) w = fmaf(W2[t * NH + k], Ws[k], w);
        d_w2s[t] = w;
    }
    if (t == 0) {
        float c = bs[0];
        for (int k = 0; k < NH; k++) c = fmaf(b2[k], Ws[k], c);
        d_c2[0] = c;
    }
}

// ---------------- CSR build ----------------
__global__ void zero_int_kernel(int* __restrict__ p, int n) {
    int i = blockIdx.x * blockDim.x + threadIdx.x;
    if (i < n) p[i] = 0;
}
__global__ void count_kernel(const int* __restrict__ dst, int* __restrict__ cnt, int e) {
    int i = blockIdx.x * blockDim.x + threadIdx.x;
    if (i < e) atomicAdd(&cnt[dst[i]], 1);
}
__global__ __launch_bounds__(SCAN_B) void blocksum_kernel(
    const int* __restrict__ cnt, int* __restrict__ bsum, int n) {
    __shared__ int s[SCAN_B];
    int t = threadIdx.x;
    int i = blockIdx.x * SCAN_B + t;
    s[t] = (i < n) ? cnt[i] : 0;
    __syncthreads();
    for (int d = SCAN_B / 2; d; d >>= 1) {
        if (t < d) s[t] += s[t + d];
        __syncthreads();
    }
    if (t == 0) bsum[blockIdx.x] = s[0];
}
__global__ __launch_bounds__(SCAN_B) void scansum_kernel(int* __restrict__ bsum, int nb) {
    __shared__ int s[SCAN_B];
    int t = threadIdx.x;
    int v = (t < nb) ? bsum[t] : 0;
    s[t] = v;
    __syncthreads();
    for (int d = 1; d < SCAN_B; d <<= 1) {
        int u = (t >= d) ? s[t - d] : 0;
        __syncthreads();
        s[t] += u;
        __syncthreads();
    }
    if (t < nb) bsum[t] = s[t] - v;
}
__global__ __launch_bounds__(SCAN_B) void scanfin_kernel(
    const int* __restrict__ cnt, const int* __restrict__ bsum,
    int* __restrict__ off, int* __restrict__ cur, int n) {
    __shared__ int s[SCAN_B];
    int t = threadIdx.x;
    int i = blockIdx.x * SCAN_B + t;
    int v = (i < n) ? cnt[i] : 0;
    s[t] = v;
    __syncthreads();
    for (int d = 1; d < SCAN_B; d <<= 1) {
        int u = (t >= d) ? s[t - d] : 0;
        __syncthreads();
        s[t] += u;
        __syncthreads();
    }
    if (i < n) {
        int o = s[t] - v + bsum[blockIdx.x];
        off[i] = o;
        cur[i] = o;
    }
}
__global__ void fill_kernel(const int* __restrict__ src, const int* __restrict__ dst,
                            int* __restrict__ cur, int* __restrict__ esrc, int e) {
    int i = blockIdx.x * blockDim.x + threadIdx.x;
    if (i < e) {
        int pos = atomicAdd(&cur[dst[i]], 1);
        esrc[pos] = src[i];
    }
}

// ---------------- node encoder: h = relu(x @ Wn + bn), 4 nodes/warp ----------------
// lane j-mapping: (2*lane, 2*lane+1); weights natural row-major in smem.
__global__ __launch_bounds__(256) void node_enc_kernel(
    const float* __restrict__ x, const float* __restrict__ Wn,
    const float* __restrict__ bn, float* __restrict__ out, int n) {
    extern __shared__ char smraw[];
    float* sW = (float*)smraw;            // 32KB natural
    float* sX = (float*)(smraw + 32768);  // 16KB
    const float4* Wn4 = (const float4*)Wn;
    float4* sW4 = (float4*)sW;
    for (int i = threadIdx.x; i < IN_NODE * NH / 4; i += 256) sW4[i] = Wn4[i];
    int warp = threadIdx.x >> 5, lane = threadIdx.x & 31;
    int base = (blockIdx.x * 8 + warp) * 4;
    float* sXw = sX + warp * 4 * IN_NODE;
#pragma unroll
    for (int m = 0; m < 4; m++) {
        int nd = base + m;
        if (nd < n) {
            const float4* xr = (const float4*)(x + (size_t)nd * IN_NODE);
            ((float4*)(sXw + m * IN_NODE))[lane] = xr[lane];
        }
    }
    __syncthreads();
    const ull* sWu = (const ull*)sW;
    float2 bv = ((const float2*)bn)[lane];
    ull zb = pk2(bv.x, bv.y);
    ull z0 = zb, z1 = zb, z2 = zb, z3 = zb;
#pragma unroll 4
    for (int k0 = 0; k0 < IN_NODE; k0 += 4) {
        float4 a0 = *(const float4*)(sXw + 0 * IN_NODE + k0);
        float4 a1 = *(const float4*)(sXw + 1 * IN_NODE + k0);
        float4 a2 = *(const float4*)(sXw + 2 * IN_NODE + k0);
        float4 a3 = *(const float4*)(sXw + 3 * IN_NODE + k0);
        const float* f0 = (const float*)&a0;
        const float* f1 = (const float*)&a1;
        const float* f2 = (const float*)&a2;
        const float* f3 = (const float*)&a3;
#pragma unroll
        for (int kk = 0; kk < 4; kk++) {
            ull w = sWu[(k0 + kk) * 32 + lane];
            z0 = fma2(dup2(f0[kk]), w, z0);
            z1 = fma2(dup2(f1[kk]), w, z1);
            z2 = fma2(dup2(f2[kk]), w, z2);
            z3 = fma2(dup2(f3[kk]), w, z3);
        }
    }
    ull zz[4] = {z0, z1, z2, z3};
#pragma unroll
    for (int m = 0; m < 4; m++) {
        int nd = base + m;
        if (nd < n) {
            float lo, hi; upk2(zz[m], lo, hi);
            ((float2*)out)[(size_t)nd * 32 + lane] =
                make_float2(fmaxf(lo, 0.f), fmaxf(hi, 0.f));
        }
    }
}

// ---------------- fused aggregate + SAGE combine (+ optional fused P/Q) ----------------
// smem: sW0(16KB) | sW1s(16KB) | sA(8KB) | sH(8KB) = 48KB
template <int DO_PQ>
__global__ __launch_bounds__(256) void combine_kernel(
    const float* __restrict__ hin, const int* __restrict__ esrc,
    const int* __restrict__ off, const int* __restrict__ cnt,
    const float* __restrict__ Wl, const float* __restrict__ bl,
    const float* __restrict__ Wr, const float* __restrict__ W1,
    float* __restrict__ houtP, float* __restrict__ Qout, int n) {
    extern __shared__ char smraw[];
    float* sW0 = (float*)smraw;              // Wl, later W1a (natural)
    float* sW1s = (float*)(smraw + 16384);   // Wr, later W1b
    float* sA = (float*)(smraw + 32768);     // agg rows, later relu(h) rows
    float* sH = (float*)(smraw + 40960);     // self rows

    {
        const float4* Wl4 = (const float4*)Wl;
        const float4* Wr4 = (const float4*)Wr;
        float4* s04 = (float4*)sW0;
        float4* s14 = (float4*)sW1s;
        for (int i = threadIdx.x; i < NH * NH / 4; i += 256) {
            s04[i] = Wl4[i];
            s14[i] = Wr4[i];
        }
    }

    int warp = threadIdx.x >> 5, lane = threadIdx.x & 31;
    int base = (blockIdx.x * 8 + warp) * 4;
    const ull* hinU = (const ull*)hin;

#pragma unroll
    for (int m = 0; m < 4; m++) {
        int nd = base + m;
        ull a = 0, h = 0;
        if (nd < n) {
            int dg = cnt[nd];
            int o = off[nd];
            h = __ldg(hinU + (size_t)nd * 32 + lane);
            int i = 0;
            for (; i + 4 <= dg; i += 4) {
                int s0 = __ldg(esrc + o + i);
                int s1 = __ldg(esrc + o + i + 1);
                int s2 = __ldg(esrc + o + i + 2);
                int s3 = __ldg(esrc + o + i + 3);
                ull v0 = __ldg(hinU + (size_t)s0 * 32 + lane);
                ull v1 = __ldg(hinU + (size_t)s1 * 32 + lane);
                ull v2 = __ldg(hinU + (size_t)s2 * 32 + lane);
                ull v3 = __ldg(hinU + (size_t)s3 * 32 + lane);
                a = add2(a, add2(add2(v0, v1), add2(v2, v3)));
            }
            for (; i < dg; i++)
                a = add2(a, __ldg(hinU + (size_t)__ldg(esrc + o + i) * 32 + lane));
            float iv = 1.f / fmaxf((float)dg, 1.f);
            a = mul2(a, dup2(iv));
        }
        int rb = (warp * 4 + m) * 32;
        ((ull*)sA)[rb + lane] = a;
        ((ull*)sH)[rb + lane] = h;
    }
    __syncthreads();

    const ull* uWl = (const ull*)sW0;
    const ull* uWr = (const ull*)sW1s;
    float2 bv = ((const float2*)bl)[lane];
    ull zbv = pk2(bv.x, bv.y);
    ull z[4] = {zbv, zbv, zbv, zbv};
#pragma unroll 4
    for (int k0 = 0; k0 < NH; k0 += 4) {
        float4 av[4], hv[4];
#pragma unroll
        for (int m = 0; m < 4; m++) {
            int rb = (warp * 4 + m) * NH;
            av[m] = *(const float4*)(sA + rb + k0);
            hv[m] = *(const float4*)(sH + rb + k0);
        }
#pragma unroll
        for (int kk = 0; kk < 4; kk++) {
            ull wl = uWl[(k0 + kk) * 32 + lane];
            ull wr = uWr[(k0 + kk) * 32 + lane];
#pragma unroll
            for (int m = 0; m < 4; m++) {
                const float* af = (const float*)&av[m];
                const float* hf = (const float*)&hv[m];
                z[m] = fma2(dup2(af[kk]), wl, z[m]);
                z[m] = fma2(dup2(hf[kk]), wr, z[m]);
            }
        }
    }

    float r0[4], r1[4];
#pragma unroll
    for (int m = 0; m < 4; m++) {
        float lo, hi; upk2(z[m], lo, hi);
        r0[m] = fmaxf(lo, 0.f);
        r1[m] = fmaxf(hi, 0.f);
    }

    if (!DO_PQ) {
#pragma unroll
        for (int m = 0; m < 4; m++) {
            int nd = base + m;
            if (nd < n)
                ((float2*)houtP)[(size_t)nd * 32 + lane] = make_float2(r0[m], r1[m]);
        }
        return;
    }

    // -------- fused P/Q: reuse weight smem --------
    __syncthreads();
    {
        const float4* Wa4 = (const float4*)W1;
        const float4* Wb4 = (const float4*)(W1 + NH * NH);
        float4* s04 = (float4*)sW0;
        float4* s14 = (float4*)sW1s;
        for (int i = threadIdx.x; i < NH * NH / 4; i += 256) {
            s04[i] = Wa4[i];
            s14[i] = Wb4[i];
        }
    }
#pragma unroll
    for (int m = 0; m < 4; m++) {
        int rb = (warp * 4 + m) * 32;
        ((ull*)sA)[rb + lane] = pk2(r0[m], r1[m]);
    }
    __syncthreads();

    const ull* uWa = (const ull*)sW0;
    const ull* uWb = (const ull*)sW1s;
    ull p[4] = {0, 0, 0, 0}, q[4] = {0, 0, 0, 0};
#pragma unroll 4
    for (int k0 = 0; k0 < NH; k0 += 4) {
        float4 hv[4];
#pragma unroll
        for (int m = 0; m < 4; m++)
            hv[m] = *(const float4*)(sA + (warp * 4 + m) * NH + k0);
#pragma unroll
        for (int kk = 0; kk < 4; kk++) {
            ull wa = uWa[(k0 + kk) * 32 + lane];
            ull wb = uWb[(k0 + kk) * 32 + lane];
#pragma unroll
            for (int m = 0; m < 4; m++) {
                const float* hf = (const float*)&hv[m];
                ull hd = dup2(hf[kk]);
                p[m] = fma2(hd, wa, p[m]);
                q[m] = fma2(hd, wb, q[m]);
            }
        }
    }
#pragma unroll
    for (int m = 0; m < 4; m++) {
        int nd = base + m;
        if (nd < n) {
            float lo, hi;
            upk2(p[m], lo, hi);
            ((float2*)houtP)[(size_t)nd * 32 + lane] = make_float2(lo, hi);
            upk2(q[m], lo, hi);
            ((float2*)Qout)[(size_t)nd * 32 + lane] = make_float2(lo, hi);
        }
    }
}

// ---------------- edge kernel: streamed 256-edge tiles, warp per 32 edges ----------------
#define ETILE 256
__global__ __launch_bounds__(256) void edge_kernel(
    const int* __restrict__ src, const int* __restrict__ dst,
    const float* __restrict__ ea, const float* __restrict__ P,
    const float* __restrict__ Q, float* __restrict__ out, int e) {
    __shared__ float sEA[ETILE * IN_EDGE];  // 32KB
    __shared__ int sS[ETILE];
    __shared__ int sD[ETILE];
    __shared__ float sOut[ETILE];
    int t = threadIdx.x, warp = t >> 5, lane = t & 31;
    int base = blockIdx.x * ETILE;
    int cnt = min(ETILE, e - base);

    // folded edge weights in registers: wc[k] = Wec[k][2lane..2lane+1]
    ull wc[IN_EDGE];
    const ull* wsrc = (const ull*)d_Wec;
#pragma unroll
    for (int k = 0; k < IN_EDGE; k++) wc[k] = wsrc[k * 32 + lane];
    float2 bv = ((const float2*)d_b1p)[lane];
    ull zb = pk2(bv.x, bv.y);
    float2 ws = ((const float2*)d_w2s)[lane];
    float c2 = d_c2[0];

    // coalesced stage of edge_attr tile + endpoints
    const float4* eag = (const float4*)(ea + (size_t)base * IN_EDGE);
    float4* eas = (float4*)sEA;
    int n4 = cnt * (IN_EDGE / 4);
    for (int i = t; i < n4; i += 256) eas[i] = eag[i];
    for (int i = t; i < cnt; i += 256) {
        sS[i] = src[base + i];
        sD[i] = dst[base + i];
    }
    __syncthreads();

    const ull* Pu = (const ull*)P;
    const ull* Qu = (const ull*)Q;
    int e0 = warp * 32;
    int e1 = min(e0 + 32, cnt);
#pragma unroll 2
    for (int j = e0; j < e1; j++) {
        int s = sS[j], d = sD[j];
        ull pv = __ldg(Pu + (size_t)s * 32 + lane);
        ull qv = __ldg(Qu + (size_t)d * 32 + lane);
        ull za = add2(add2(pv, qv), zb);
        ull zc = 0;
        const float4* row = (const float4*)(sEA + j * IN_EDGE);
#pragma unroll
        for (int c = 0; c < 8; c++) {
            float4 v = row[c];  // uniform smem -> broadcast
            za = fma2(dup2(v.x), wc[c * 4 + 0], za);
            zc = fma2(dup2(v.y), wc[c * 4 + 1], zc);
            za = fma2(dup2(v.z), wc[c * 4 + 2], za);
            zc = fma2(dup2(v.w), wc[c * 4 + 3], zc);
        }
        float lo, hi; upk2(add2(za, zc), lo, hi);
        float v = fmaxf(lo, 0.f) * ws.x + fmaxf(hi, 0.f) * ws.y;
#pragma unroll
        for (int o = 16; o; o >>= 1) v += __shfl_down_sync(0xffffffffu, v, o);
        if (lane == 0) sOut[j] = v + c2;
    }
    __syncwarp();
    int idx = e0 + lane;
    if (idx < cnt) out[base + idx] = sOut[idx];
}

// ---------------- launch ----------------
extern "C" void kernel_launch(void* const* d_in, const int* in_sizes, int n_in,
                              void* d_out, int out_size) {
    const float* x   = (const float*)d_in[0];
    const int* eidx  = (const int*)d_in[1];
    const float* ea  = (const float*)d_in[2];
    const float* Wn  = (const float*)d_in[3];
    const float* bn  = (const float*)d_in[4];
    const float* We  = (const float*)d_in[5];
    const float* be  = (const float*)d_in[6];
    const float* Wl0 = (const float*)d_in[7];
    const float* bl0 = (const float*)d_in[8];
    const float* Wr0 = (const float*)d_in[9];
    const float* Wl1 = (const float*)d_in[10];
    const float* bl1 = (const float*)d_in[11];
    const float* Wr1 = (const float*)d_in[12];
    const float* W1  = (const float*)d_in[13];
    const float* b1  = (const float*)d_in[14];
    const float* W2  = (const float*)d_in[15];
    const float* b2  = (const float*)d_in[16];
    const float* Ws  = (const float*)d_in[17];
    const float* bs  = (const float*)d_in[18];
    float* out = (float*)d_out;

    int n = in_sizes[0] / IN_NODE;
    int e = in_sizes[2] / IN_EDGE;
    const int* src = eidx;
    const int* dst = eidx + e;

    float *A, *B, *Q;
    int *cnt, *off, *cur, *bsum, *esrc;
    cudaGetSymbolAddress((void**)&A, d_A);
    cudaGetSymbolAddress((void**)&B, d_B);
    cudaGetSymbolAddress((void**)&Q, d_Qb);
    cudaGetSymbolAddress((void**)&cnt, d_cnt);
    cudaGetSymbolAddress((void**)&off, d_off);
    cudaGetSymbolAddress((void**)&cur, d_cur);
    cudaGetSymbolAddress((void**)&bsum, d_bsum);
    cudaGetSymbolAddress((void**)&esrc, d_esrc);

    static bool attrs_set = false;
    if (!attrs_set) {
        cudaFuncSetAttribute(node_enc_kernel, cudaFuncAttributeMaxDynamicSharedMemorySize, 49152);
        cudaFuncSetAttribute(combine_kernel<0>, cudaFuncAttributeMaxDynamicSharedMemorySize, 49152);
        cudaFuncSetAttribute(combine_kernel<1>, cudaFuncAttributeMaxDynamicSharedMemorySize, 49152);
        attrs_set = true;
    }

    int nb_n = (n + 255) / 256;
    int nb_e = (e + 255) / 256;
    int nb_w = (n + 31) / 32;            // combine: 4 nodes/warp, 8 warps/block
    int nb_sc = (n + SCAN_B - 1) / SCAN_B;
    int nb_ed = (e + ETILE - 1) / ETILE;

    fold_kernel<<<1, 256>>>(W1, b1, We, be, W2, b2, Ws, bs);

    // CSR build
    zero_int_kernel<<<nb_n, 256>>>(cnt, n);
    count_kernel<<<nb_e, 256>>>(dst, cnt, e);
    blocksum_kernel<<<nb_sc, SCAN_B>>>(cnt, bsum, n);
    scansum_kernel<<<1, SCAN_B>>>(bsum, nb_sc);
    scanfin_kernel<<<nb_sc, SCAN_B>>>(cnt, bsum, off, cur, n);
    fill_kernel<<<nb_e, 256>>>(src, dst, cur, esrc, e);

    // node encoder -> A
    node_enc_kernel<<<nb_w, 256, 49152>>>(x, Wn, bn, A, n);

    // layer 0: A -> B
    combine_kernel<0><<<nb_w, 256, 49152>>>(A, esrc, off, cnt, Wl0, bl0, Wr0, nullptr, B, nullptr, n);

    // layer 1 + fused PQ: B -> P(A), Q
    combine_kernel<1><<<nb_w, 256, 49152>>>(B, esrc, off, cnt, Wl1, bl1, Wr1, W1, A, Q, n);

    // edge output (natural order, streamed ea)
    edge_kernel<<<nb_ed, 256>>>(src, dst, ea, A, Q, out, e);
}